// round 3
// baseline (speedup 1.0000x reference)
#include <cuda_runtime.h>
#include <cstdint>

// Binarized NAND-conv net, one thread = one image, fully register-resident.
// bit=1 <=> +1. D = #mismatches over T taps; NAND out bit = (D >= T/2).
//  L0: 1x28x28 ->16x14x14 (T=4, via shfl LUT)   L1: ->16x7x7 (T=64)
//  L2: ->16x6x6  L3: ->16x3x3  L4: ->16x1x1 (all T=64)   L5: ->10 (T=16)
//
// KEY FIX vs prior round: __launch_bounds__(64, 1) lets ptxas use up to 255
// registers so the activation arrays are NOT spilled to local memory.
// Occupancy is grid-limited (32768 threads total), so regs are free.

#define IMGS_PER_BLOCK 64
#define NTHREADS 64
#define NWORDS (IMGS_PER_BLOCK * 784 / 32)   // 1568

// 16-output-channel XNOR-popcount NAND step, T=64. W must be a register array.
__device__ __forceinline__ uint32_t nand16(uint64_t a, const uint64_t* W) {
    uint32_t acc = 0;
#pragma unroll
    for (int oc = 0; oc < 16; oc++) {
        uint64_t x = a ^ W[oc];
        uint32_t D = __popc((uint32_t)x) + __popc((uint32_t)(x >> 32)) + 32;
        acc |= (D >> 6) << oc;   // 1 iff mismatches >= 32
    }
    return acc;
}

__global__ void __launch_bounds__(NTHREADS, 1)
bnn_mnist_kernel(const float* __restrict__ x,
                 const float* __restrict__ w0, const float* __restrict__ w1,
                 const float* __restrict__ w2, const float* __restrict__ w3,
                 const float* __restrict__ w4, const float* __restrict__ w5,
                 float* __restrict__ out, int B)
{
    __shared__ uint32_t sbits[NWORDS + 1];
    __shared__ uint64_t sw_sh[4][16];
    __shared__ uint32_t sw0b[16];
    __shared__ uint32_t sw5s[10];

    const int tid = threadIdx.x;
    const int b0 = blockIdx.x * IMGS_PER_BLOCK;

    // ---- weight prep (tiny, redundant per block) ----
    {
        int L = tid >> 4, oc = tid & 15;
        const float* wp = (L == 0 ? w1 : L == 1 ? w2 : L == 2 ? w3 : w4) + oc * 64;
        uint64_t v = 0;
#pragma unroll
        for (int ic = 0; ic < 16; ic++)
#pragma unroll
            for (int tap = 0; tap < 4; tap++)
                if (wp[ic * 4 + tap] > 0.0f) v |= 1ull << (tap * 16 + ic);
        sw_sh[L][oc] = v;
    }
    if (tid < 16) {
        uint32_t v = 0;
#pragma unroll
        for (int k = 0; k < 4; k++)
            if (w0[tid * 4 + k] > 0.0f) v |= 1u << k;
        sw0b[tid] = v;
    }
    if (tid < 10) {
        uint32_t v = 0;
#pragma unroll
        for (int ic = 0; ic < 16; ic++)
            if (w5[tid * 16 + ic] > 0.0f) v |= 1u << ic;
        sw5s[tid] = v;
    }
    if (tid == 0) sbits[NWORDS] = 0;

    // ---- coalesced load + binarize (ballot pack) ----
    {
        const int lane = tid & 31;
        const int warp = tid >> 5;
        const float* chunk = x + (size_t)b0 * 784;
        const int nfloats = min(IMGS_PER_BLOCK, max(B - b0, 0)) * 784;
        for (int w = warp; w < NWORDS; w += (NTHREADS / 32)) {
            int f = w * 32 + lane;
            float v = (f < nfloats) ? chunk[f] : 0.0f;
            unsigned b = __ballot_sync(0xFFFFFFFFu, v > 0.0f);
            if (lane == 0) sbits[w] = b;
        }
    }
    __syncthreads();

    const int img = b0 + tid;
    const int bitbase = tid * 784;

    // ---- per-lane L0 LUT value: lane l holds LUT[l & 15] ----
    uint32_t lutv;
    {
        const int patch = tid & 15;
        uint32_t a = 0;
#pragma unroll
        for (int c = 0; c < 16; c++)
            a |= (uint32_t)(__popc((patch ^ sw0b[c]) & 0xFu) >= 2) << c;
        lutv = a;
    }

    // ---- L0 fused into L1 ----
    uint64_t W[16];
#pragma unroll
    for (int k = 0; k < 16; k++) W[k] = sw_sh[0][k];

    uint32_t act1[49];
#pragma unroll
    for (int i = 0; i < 7; i++) {
        uint32_t r[2][14];
#pragma unroll
        for (int rr = 0; rr < 2; rr++) {
            const int bpT = bitbase + 28 * (4 * i + 2 * rr);
            const int bpB = bpT + 28;
            uint32_t rT = __funnelshift_r(sbits[bpT >> 5], sbits[(bpT >> 5) + 1], bpT & 31) & 0x0FFFFFFFu;
            uint32_t rB = __funnelshift_r(sbits[bpB >> 5], sbits[(bpB >> 5) + 1], bpB & 31) & 0x0FFFFFFFu;
#pragma unroll
            for (int j = 0; j < 14; j++) {
                uint32_t a = ((rT >> (2 * j)) & 3u) | (((rB >> (2 * j)) & 3u) << 2);
                r[rr][j] = (uint32_t)__shfl_sync(0xFFFFFFFFu, lutv, (int)a) & 0xFFFFu;
            }
        }
#pragma unroll
        for (int j = 0; j < 7; j++) {
            uint64_t a64 = (uint64_t)r[0][2 * j] | ((uint64_t)r[0][2 * j + 1] << 16)
                         | ((uint64_t)r[1][2 * j] << 32) | ((uint64_t)r[1][2 * j + 1] << 48);
            act1[i * 7 + j] = nand16(a64, W);
        }
    }

    // ---- L2: 7x7 -> 6x6, stride 1 ----
#pragma unroll
    for (int k = 0; k < 16; k++) W[k] = sw_sh[1][k];
    uint32_t act2[36];
#pragma unroll
    for (int i = 0; i < 6; i++)
#pragma unroll
        for (int j = 0; j < 6; j++) {
            const int p = i * 7 + j;
            uint64_t a64 = (uint64_t)act1[p] | ((uint64_t)act1[p + 1] << 16)
                         | ((uint64_t)act1[p + 7] << 32) | ((uint64_t)act1[p + 8] << 48);
            act2[i * 6 + j] = nand16(a64, W);
        }

    // ---- L3: 6x6 -> 3x3, stride 2 ----
#pragma unroll
    for (int k = 0; k < 16; k++) W[k] = sw_sh[2][k];
    uint32_t act3[9];
#pragma unroll
    for (int i = 0; i < 3; i++)
#pragma unroll
        for (int j = 0; j < 3; j++) {
            const int p = (2 * i) * 6 + 2 * j;
            uint64_t a64 = (uint64_t)act2[p] | ((uint64_t)act2[p + 1] << 16)
                         | ((uint64_t)act2[p + 6] << 32) | ((uint64_t)act2[p + 7] << 48);
            act3[i * 3 + j] = nand16(a64, W);
        }

    // ---- L4: 3x3 -> 1x1, stride 2 ----
#pragma unroll
    for (int k = 0; k < 16; k++) W[k] = sw_sh[3][k];
    uint32_t act4;
    {
        uint64_t a64 = (uint64_t)act3[0] | ((uint64_t)act3[1] << 16)
                     | ((uint64_t)act3[3] << 32) | ((uint64_t)act3[4] << 48);
        act4 = nand16(a64, W);
    }

    // ---- L5: 16 -> 10 classes ----
    if (img < B) {
        float* o = out + (size_t)img * 10;
#pragma unroll
        for (int oc = 0; oc < 10; oc++) {
            uint32_t D = __popc((act4 ^ sw5s[oc]) & 0xFFFFu);
            o[oc] = (D >= 8) ? 1.0f : -1.0f;
        }
    }
}

extern "C" void kernel_launch(void* const* d_in, const int* in_sizes, int n_in,
                              void* d_out, int out_size)
{
    const float* x  = (const float*)d_in[0];
    const float* w0 = (const float*)d_in[1];
    const float* w1 = (const float*)d_in[2];
    const float* w2 = (const float*)d_in[3];
    const float* w3 = (const float*)d_in[4];
    const float* w4 = (const float*)d_in[5];
    const float* w5 = (const float*)d_in[6];
    float* out = (float*)d_out;

    int B = in_sizes[0] / 784;
    int grid = (B + IMGS_PER_BLOCK - 1) / IMGS_PER_BLOCK;
    bnn_mnist_kernel<<<grid, NTHREADS>>>(x, w0, w1, w2, w3, w4, w5, out, B);
}

// round 4
// speedup vs baseline: 4.1544x; 4.1544x over previous
#include <cuda_runtime.h>
#include <cstdint>

// Binarized NAND-conv net. One thread = one image. Activations live in
// per-thread SHARED MEMORY rows (conflict-free strides), layer loops are
// compact (not spatially unrolled) so code fits the L0 I-cache and nothing
// spills to local memory.
//
//  L0: 1x28x28 ->16x14x14 (T=4, shfl LUT, fused into L1)
//  L1: ->16x7x7  L2: ->16x6x6  L3: ->16x3x3  L4: ->16x1x1 (T=64)
//  L5: ->10 (T=16).  bit=1 <=> +1 ; out bit = (#mismatch >= T/2).

#define IMGS_PER_BLOCK 64
#define NTHREADS 64
#define NWORDS (IMGS_PER_BLOCK * 784 / 32)   // 1568
#define S1 51   // act1 row stride (words); gcd(51,32)=1 -> conflict-free
#define S2 37   // act2 row stride (words); gcd(37,32)=1 -> conflict-free

__device__ __forceinline__ uint32_t nand16(uint64_t a, const uint64_t (&W)[16]) {
    uint32_t acc = 0;
#pragma unroll
    for (int oc = 0; oc < 16; oc++) {
        uint64_t x = a ^ W[oc];
        uint32_t D = __popc((uint32_t)x) + __popc((uint32_t)(x >> 32)) + 32;
        acc |= (D >> 6) << oc;   // 1 iff mismatches >= 32 (D in [32,96])
    }
    return acc;
}

__global__ void __launch_bounds__(NTHREADS, 1)
bnn_mnist_kernel(const float* __restrict__ x,
                 const float* __restrict__ w0, const float* __restrict__ w1,
                 const float* __restrict__ w2, const float* __restrict__ w3,
                 const float* __restrict__ w4, const float* __restrict__ w5,
                 float* __restrict__ out, int B)
{
    __shared__ uint32_t sbits[NWORDS + 1];
    __shared__ uint64_t sw_sh[4][16];
    __shared__ uint32_t sw0b[16];
    __shared__ uint32_t sw5s[10];
    __shared__ uint32_t sact1[IMGS_PER_BLOCK * S1];
    __shared__ uint32_t sact2[IMGS_PER_BLOCK * S2];

    const int tid = threadIdx.x;
    const int b0 = blockIdx.x * IMGS_PER_BLOCK;

    // ---- weight prep ----
    {
        int L = tid >> 4, oc = tid & 15;
        const float* wp = (L == 0 ? w1 : L == 1 ? w2 : L == 2 ? w3 : w4) + oc * 64;
        uint64_t v = 0;
#pragma unroll
        for (int ic = 0; ic < 16; ic++)
#pragma unroll
            for (int tap = 0; tap < 4; tap++)
                if (wp[ic * 4 + tap] > 0.0f) v |= 1ull << (tap * 16 + ic);
        sw_sh[L][oc] = v;
    }
    if (tid < 16) {
        uint32_t v = 0;
#pragma unroll
        for (int k = 0; k < 4; k++)
            if (w0[tid * 4 + k] > 0.0f) v |= 1u << k;
        sw0b[tid] = v;
    }
    if (tid < 10) {
        uint32_t v = 0;
#pragma unroll
        for (int ic = 0; ic < 16; ic++)
            if (w5[tid * 16 + ic] > 0.0f) v |= 1u << ic;
        sw5s[tid] = v;
    }
    if (tid == 0) sbits[NWORDS] = 0;

    // ---- load + binarize + pack ----
    const int lane = tid & 31;
    const int warp = tid >> 5;
    const float* chunk = x + (size_t)b0 * 784;
    if (b0 + IMGS_PER_BLOCK <= B) {
        // fast path: float4 loads, nibble pack, shfl_xor OR-reduce in 8-lane groups
        const float4* c4 = (const float4*)chunk;
        for (int ch = warp; ch < NWORDS / 4; ch += (NTHREADS / 32)) {
            float4 v = c4[ch * 32 + lane];
            uint32_t nib = (uint32_t)(v.x > 0.0f) | ((uint32_t)(v.y > 0.0f) << 1)
                         | ((uint32_t)(v.z > 0.0f) << 2) | ((uint32_t)(v.w > 0.0f) << 3);
            uint32_t val = nib << (4 * (lane & 7));
            val |= __shfl_xor_sync(0xFFFFFFFFu, val, 1);
            val |= __shfl_xor_sync(0xFFFFFFFFu, val, 2);
            val |= __shfl_xor_sync(0xFFFFFFFFu, val, 4);
            if ((lane & 7) == 0) sbits[ch * 4 + (lane >> 3)] = val;
        }
    } else {
        const int nfloats = max(min(IMGS_PER_BLOCK, B - b0), 0) * 784;
        for (int w = warp; w < NWORDS; w += (NTHREADS / 32)) {
            int f = w * 32 + lane;
            float v = (f < nfloats) ? chunk[f] : 0.0f;
            unsigned b = __ballot_sync(0xFFFFFFFFu, v > 0.0f);
            if (lane == 0) sbits[w] = b;
        }
    }
    __syncthreads();

    // per-lane L0 LUT: lane l holds LUT[l & 15] (16-bit channel vector)
    uint32_t lutv;
    {
        const int patch = tid & 15;
        uint32_t a = 0;
#pragma unroll
        for (int c = 0; c < 16; c++)
            a |= (uint32_t)(__popc((patch ^ sw0b[c]) & 0xFu) >= 2) << c;
        lutv = a;
    }

    const int img = b0 + tid;
    const int bitbase = tid * 784;
    const int row1 = tid * S1;
    const int row2 = tid * S2;
    uint64_t W[16];

    // ---- L0 fused into L1: 28x28 bits -> act1 (16ch x 7x7) ----
#pragma unroll
    for (int k = 0; k < 16; k++) W[k] = sw_sh[0][k];
    for (int i = 0; i < 7; i++) {
        const int r0 = bitbase + 112 * i;   // input row 4i
        uint32_t rT0, rB0, rT1, rB1;
        {
            int bp = r0;
            rT0 = __funnelshift_r(sbits[bp >> 5], sbits[(bp >> 5) + 1], bp) & 0x0FFFFFFFu;
            bp = r0 + 28;
            rB0 = __funnelshift_r(sbits[bp >> 5], sbits[(bp >> 5) + 1], bp) & 0x0FFFFFFFu;
            bp = r0 + 56;
            rT1 = __funnelshift_r(sbits[bp >> 5], sbits[(bp >> 5) + 1], bp) & 0x0FFFFFFFu;
            bp = r0 + 84;
            rB1 = __funnelshift_r(sbits[bp >> 5], sbits[(bp >> 5) + 1], bp) & 0x0FFFFFFFu;
        }
        for (int j = 0; j < 7; j++) {
            const int s = 4 * j;
            uint32_t pA = ((rT0 >> s) & 3u) | (((rB0 >> s) & 3u) << 2);
            uint32_t pB = ((rT0 >> (s + 2)) & 3u) | (((rB0 >> (s + 2)) & 3u) << 2);
            uint32_t pC = ((rT1 >> s) & 3u) | (((rB1 >> s) & 3u) << 2);
            uint32_t pD = ((rT1 >> (s + 2)) & 3u) | (((rB1 >> (s + 2)) & 3u) << 2);
            uint32_t v00 = (uint32_t)__shfl_sync(0xFFFFFFFFu, lutv, (int)pA) & 0xFFFFu;
            uint32_t v01 = (uint32_t)__shfl_sync(0xFFFFFFFFu, lutv, (int)pB) & 0xFFFFu;
            uint32_t v10 = (uint32_t)__shfl_sync(0xFFFFFFFFu, lutv, (int)pC) & 0xFFFFu;
            uint32_t v11 = (uint32_t)__shfl_sync(0xFFFFFFFFu, lutv, (int)pD) & 0xFFFFu;
            uint64_t a64 = (uint64_t)v00 | ((uint64_t)v01 << 16)
                         | ((uint64_t)v10 << 32) | ((uint64_t)v11 << 48);
            sact1[row1 + i * 7 + j] = nand16(a64, W);
        }
    }

    // ---- L2: 7x7 -> 6x6 (stride 1) ----
#pragma unroll
    for (int k = 0; k < 16; k++) W[k] = sw_sh[1][k];
    for (int i = 0; i < 6; i++)
        for (int j = 0; j < 6; j++) {
            const int p = row1 + i * 7 + j;
            uint64_t a64 = (uint64_t)sact1[p] | ((uint64_t)sact1[p + 1] << 16)
                         | ((uint64_t)sact1[p + 7] << 32) | ((uint64_t)sact1[p + 8] << 48);
            sact2[row2 + i * 6 + j] = nand16(a64, W);
        }

    // ---- L3: 6x6 -> 3x3 (stride 2); reuse sact1 for output ----
#pragma unroll
    for (int k = 0; k < 16; k++) W[k] = sw_sh[2][k];
    for (int i = 0; i < 3; i++)
        for (int j = 0; j < 3; j++) {
            const int p = row2 + 12 * i + 2 * j;
            uint64_t a64 = (uint64_t)sact2[p] | ((uint64_t)sact2[p + 1] << 16)
                         | ((uint64_t)sact2[p + 6] << 32) | ((uint64_t)sact2[p + 7] << 48);
            sact1[row1 + i * 3 + j] = nand16(a64, W);
        }

    // ---- L4: 3x3 -> 1x1 (stride 2) ----
#pragma unroll
    for (int k = 0; k < 16; k++) W[k] = sw_sh[3][k];
    uint32_t act4;
    {
        uint64_t a64 = (uint64_t)sact1[row1 + 0] | ((uint64_t)sact1[row1 + 1] << 16)
                     | ((uint64_t)sact1[row1 + 3] << 32) | ((uint64_t)sact1[row1 + 4] << 48);
        act4 = nand16(a64, W);
    }

    // ---- L5: 16 -> 10 ----
    if (img < B) {
        float* o = out + (size_t)img * 10;
#pragma unroll
        for (int oc = 0; oc < 10; oc++) {
            uint32_t D = __popc((act4 ^ sw5s[oc]) & 0xFFFFu);
            o[oc] = (D >= 8) ? 1.0f : -1.0f;
        }
    }
}

extern "C" void kernel_launch(void* const* d_in, const int* in_sizes, int n_in,
                              void* d_out, int out_size)
{
    const float* x  = (const float*)d_in[0];
    const float* w0 = (const float*)d_in[1];
    const float* w1 = (const float*)d_in[2];
    const float* w2 = (const float*)d_in[3];
    const float* w3 = (const float*)d_in[4];
    const float* w4 = (const float*)d_in[5];
    const float* w5 = (const float*)d_in[6];
    float* out = (float*)d_out;

    int B = in_sizes[0] / 784;
    int grid = (B + IMGS_PER_BLOCK - 1) / IMGS_PER_BLOCK;
    bnn_mnist_kernel<<<grid, NTHREADS>>>(x, w0, w1, w2, w3, w4, w5, out, B);
}